// round 10
// baseline (speedup 1.0000x reference)
#include <cuda_runtime.h>
#include <cuda_fp16.h>
#include <cstdint>

// ToeplitzCausalLinear via single-product fp16 mma.sync GEMM.
// out = fp16(X) @ fp16(W) + bias, W[k][n] = w[n-k] (n>=k), fp32 accumulate.
// rel_err ~2.9e-4 (measured R8) under the 1e-3 threshold.
// R9: 4 warps / 64x64 warp tile -> LDSM:MMA ratio 4:1, more acc ILP.

#define S_DIM 1024
#define M_DIM 32768
#define BM 128
#define BN 128
#define BK 64
#define ROWB 144                 // 128B data + 16B pad; conflict-free ldmatrix phases
#define TILE_B (128 * ROWB)      // 18432 B
#define A_HI 0
#define B_HI (1 * TILE_B)
#define STAGE (2 * TILE_B)       // 36864
#define NSTAGE 3
#define SMEM_TOTAL (NSTAGE * STAGE)  // 110592

// ------------- static scratch (no allocations) -------------
__device__ __align__(1024) __half g_Xhi[(size_t)M_DIM * S_DIM];
__device__ __align__(1024) __half g_Whi[(size_t)S_DIM * S_DIM]; // [n][k]

// ------------- helpers -------------
__device__ __forceinline__ uint32_t smem_u32(const void* p) {
    uint32_t a;
    asm("{ .reg .u64 t; cvta.to.shared.u64 t, %1; cvt.u32.u64 %0, t; }" : "=r"(a) : "l"(p));
    return a;
}
__device__ __forceinline__ void cp16(uint32_t s, const void* g) {
    asm volatile("cp.async.cg.shared.global [%0], [%1], 16;" :: "r"(s), "l"(g) : "memory");
}
__device__ __forceinline__ void ldsm4(uint32_t addr, uint32_t r[4]) {
    asm volatile("ldmatrix.sync.aligned.m8n8.x4.shared.b16 {%0,%1,%2,%3}, [%4];"
                 : "=r"(r[0]), "=r"(r[1]), "=r"(r[2]), "=r"(r[3]) : "r"(addr));
}
__device__ __forceinline__ void mma16816(float c[4], const uint32_t a[4], const uint32_t b0, const uint32_t b1) {
    asm volatile("mma.sync.aligned.m16n8k16.row.col.f32.f16.f16.f32 "
                 "{%0,%1,%2,%3}, {%4,%5,%6,%7}, {%8,%9}, {%0,%1,%2,%3};"
                 : "+f"(c[0]), "+f"(c[1]), "+f"(c[2]), "+f"(c[3])
                 : "r"(a[0]), "r"(a[1]), "r"(a[2]), "r"(a[3]), "r"(b0), "r"(b1));
}

// ------------- prepass -------------
__global__ __launch_bounds__(256) void convert_x_kernel(const float* __restrict__ X) {
    size_t i = ((size_t)blockIdx.x * 256 + threadIdx.x) * 4;
    float4 v = *reinterpret_cast<const float4*>(X + i);
    __half2* ph = reinterpret_cast<__half2*>(g_Xhi + i);
    ph[0] = __halves2half2(__float2half_rn(v.x), __float2half_rn(v.y));
    ph[1] = __halves2half2(__float2half_rn(v.z), __float2half_rn(v.w));
}
__global__ __launch_bounds__(256) void build_w_kernel(const float* __restrict__ w) {
    int idx = blockIdx.x * 256 + threadIdx.x;      // 0 .. S*S-1
    int n = idx >> 10, k = idx & (S_DIM - 1);
    float v = (n >= k) ? w[n - k] : 0.0f;
    g_Whi[idx] = __float2half_rn(v);
}

// ------------- main GEMM: 128 threads, 4 warps, 64x64 warp tile -------------
__global__ __launch_bounds__(128, 2)
void toeplitz_hmma(const float* __restrict__ bias, float* __restrict__ C) {
    extern __shared__ __align__(128) char smem[];
    const uint32_t sb = smem_u32(smem);
    const int tid = threadIdx.x;
    const int lane = tid & 31, wid = tid >> 5;
    const int warp_m = wid >> 1;                   // 0..1 -> 64 rows
    const int warp_n = wid & 1;                    // 0..1 -> 64 cols
    const int jb = blockIdx.x, ib = blockIdx.y;
    const int rowBase = ib * BM, colBase = jb * BN;
    const int nKB = (jb + 1) * 2;                  // causal: k < colBase + BN, BK=64

    float acc[4][8][4];
    #pragma unroll
    for (int i = 0; i < 4; i++)
        #pragma unroll
        for (int j = 0; j < 8; j++)
            #pragma unroll
            for (int k = 0; k < 4; k++) acc[i][j][k] = 0.0f;

    // loader: thread t -> one full 128B row of each tile (8 x 16B chunks)
    const __half* gA0 = g_Xhi + (size_t)(rowBase + tid) * S_DIM;
    const __half* gB0 = g_Whi + (size_t)(colBase + tid) * S_DIM;
    const uint32_t sRow = tid * ROWB;

    auto issue = [&](int kb) {
        const uint32_t stBase = sb + (kb % NSTAGE) * STAGE;
        const int gk = kb * BK;
        #pragma unroll
        for (int c = 0; c < 8; c++) {
            cp16(stBase + A_HI + sRow + c * 16, gA0 + gk + c * 8);
            cp16(stBase + B_HI + sRow + c * 16, gB0 + gk + c * 8);
        }
        asm volatile("cp.async.commit_group;" ::: "memory");
    };

    // ldmatrix per-lane address components
    const int aRow = (lane & 7) + ((lane >> 3) & 1) * 8;  // + m_base
    const uint32_t aKof = (lane >> 4) * 16;               // k-half byte offset
    const int bRow = (lane & 7) + (lane >> 4) * 8;        // + n_base
    const uint32_t bKof = ((lane >> 3) & 1) * 16;

    issue(0);
    if (nKB > 1) issue(1);
    for (int kb = 0; kb < nKB; kb++) {
        if (kb + 1 < nKB) {
            asm volatile("cp.async.wait_group 1;" ::: "memory");
        } else {
            asm volatile("cp.async.wait_group 0;" ::: "memory");
        }
        __syncthreads();               // stage kb visible; stage (kb+2)%3 free
        if (kb + 2 < nKB) issue(kb + 2);

        const uint32_t stBase = sb + (kb % NSTAGE) * STAGE;
        #pragma unroll
        for (int k16 = 0; k16 < 4; k16++) {
            const uint32_t kByte = k16 * 32;
            uint32_t bh[4][4];
            #pragma unroll
            for (int ng = 0; ng < 4; ng++) {
                const int n_base = warp_n * 64 + ng * 16;
                ldsm4(stBase + B_HI + (uint32_t)(n_base + bRow) * ROWB + kByte + bKof, bh[ng]);
            }
            uint32_t ah[4][4];
            #pragma unroll
            for (int mt = 0; mt < 4; mt++) {
                const int m_base = warp_m * 64 + mt * 16;
                ldsm4(stBase + A_HI + (uint32_t)(m_base + aRow) * ROWB + kByte + aKof, ah[mt]);
            }
            #pragma unroll
            for (int mt = 0; mt < 4; mt++)
                #pragma unroll
                for (int ng = 0; ng < 4; ng++) {
                    mma16816(acc[mt][ng * 2 + 0], ah[mt], bh[ng][0], bh[ng][1]);
                    mma16816(acc[mt][ng * 2 + 1], ah[mt], bh[ng][2], bh[ng][3]);
                }
        }
    }

    // ---- epilogue: + bias, float2 stores ----
    #pragma unroll
    for (int mt = 0; mt < 4; mt++) {
        const int r0 = rowBase + warp_m * 64 + mt * 16 + (lane >> 2);
        #pragma unroll
        for (int nt = 0; nt < 8; nt++) {
            const int col = colBase + warp_n * 64 + nt * 8 + (lane & 3) * 2;
            const float2 bv = *reinterpret_cast<const float2*>(bias + col);
            float2 o0, o1;
            o0.x = acc[mt][nt][0] + bv.x; o0.y = acc[mt][nt][1] + bv.y;
            o1.x = acc[mt][nt][2] + bv.x; o1.y = acc[mt][nt][3] + bv.y;
            *reinterpret_cast<float2*>(C + (size_t)r0 * S_DIM + col) = o0;
            *reinterpret_cast<float2*>(C + (size_t)(r0 + 8) * S_DIM + col) = o1;
        }
    }
}

// ------------- launch -------------
extern "C" void kernel_launch(void* const* d_in, const int* in_sizes, int n_in,
                              void* d_out, int out_size) {
    const float* x    = (const float*)d_in[0];   // (32768, 1024)
    const float* w    = (const float*)d_in[1];   // (1, 1024)
    const float* bias = (const float*)d_in[2];   // (1024,)
    float* out = (float*)d_out;
    (void)in_sizes; (void)n_in; (void)out_size;

    cudaFuncSetAttribute(toeplitz_hmma,
                         cudaFuncAttributeMaxDynamicSharedMemorySize, SMEM_TOTAL);

    convert_x_kernel<<<(unsigned)((size_t)M_DIM * S_DIM / (256 * 4)), 256>>>(x);
    build_w_kernel<<<(S_DIM * S_DIM) / 256, 256>>>(w);

    dim3 grid(S_DIM / BN, M_DIM / BM);           // (8, 256)
    toeplitz_hmma<<<grid, 128, SMEM_TOTAL>>>(bias, out);
}

// round 11
// speedup vs baseline: 1.1772x; 1.1772x over previous
#include <cuda_runtime.h>
#include <cuda_fp16.h>
#include <cstdint>

// ToeplitzCausalLinear via single-product fp16 mma.sync GEMM.
// out = fp16(X) @ fp16(W) + bias, W[k][n] = w[n-k] (n>=k), fp32 accumulate.
// rel_err 2.92e-4 measured (R8), threshold 1e-3.
// R10: R8 config (8 warps, 64x32 warp tile, 3-stage cp.async) +
//      longest-first CTA order (jb reversed) + fused prepass launch.

#define S_DIM 1024
#define M_DIM 32768
#define BM 128
#define BN 128
#define BK 64
#define ROWB 144                 // 128B data + 16B pad; conflict-free ldmatrix phases
#define TILE_B (128 * ROWB)      // 18432 B
#define A_HI 0
#define B_HI (1 * TILE_B)
#define STAGE (2 * TILE_B)       // 36864
#define NSTAGE 3
#define SMEM_TOTAL (NSTAGE * STAGE)  // 110592

// ------------- static scratch (no allocations) -------------
__device__ __align__(1024) __half g_Xhi[(size_t)M_DIM * S_DIM];
__device__ __align__(1024) __half g_Whi[(size_t)S_DIM * S_DIM]; // [n][k]

// ------------- helpers -------------
__device__ __forceinline__ uint32_t smem_u32(const void* p) {
    uint32_t a;
    asm("{ .reg .u64 t; cvta.to.shared.u64 t, %1; cvt.u32.u64 %0, t; }" : "=r"(a) : "l"(p));
    return a;
}
__device__ __forceinline__ void cp16(uint32_t s, const void* g) {
    asm volatile("cp.async.cg.shared.global [%0], [%1], 16;" :: "r"(s), "l"(g) : "memory");
}
__device__ __forceinline__ void ldsm4(uint32_t addr, uint32_t r[4]) {
    asm volatile("ldmatrix.sync.aligned.m8n8.x4.shared.b16 {%0,%1,%2,%3}, [%4];"
                 : "=r"(r[0]), "=r"(r[1]), "=r"(r[2]), "=r"(r[3]) : "r"(addr));
}
__device__ __forceinline__ void mma16816(float c[4], const uint32_t a[4], const uint32_t b0, const uint32_t b1) {
    asm volatile("mma.sync.aligned.m16n8k16.row.col.f32.f16.f16.f32 "
                 "{%0,%1,%2,%3}, {%4,%5,%6,%7}, {%8,%9}, {%0,%1,%2,%3};"
                 : "+f"(c[0]), "+f"(c[1]), "+f"(c[2]), "+f"(c[3])
                 : "r"(a[0]), "r"(a[1]), "r"(a[2]), "r"(a[3]), "r"(b0), "r"(b1));
}

// ------------- fused prepass: blocks [0,32768) convert X, [32768,36864) build W -------------
#define XBLOCKS 32768
__global__ __launch_bounds__(256) void prepass_kernel(const float* __restrict__ X,
                                                      const float* __restrict__ w) {
    if (blockIdx.x < XBLOCKS) {
        size_t i = ((size_t)blockIdx.x * 256 + threadIdx.x) * 4;
        float4 v = *reinterpret_cast<const float4*>(X + i);
        __half2* ph = reinterpret_cast<__half2*>(g_Xhi + i);
        ph[0] = __halves2half2(__float2half_rn(v.x), __float2half_rn(v.y));
        ph[1] = __halves2half2(__float2half_rn(v.z), __float2half_rn(v.w));
    } else {
        int idx = (blockIdx.x - XBLOCKS) * 256 + threadIdx.x;   // 0 .. S*S-1
        int n = idx >> 10, k = idx & (S_DIM - 1);
        float v = (n >= k) ? w[n - k] : 0.0f;
        g_Whi[idx] = __float2half_rn(v);
    }
}

// ------------- main GEMM: 256 threads, 8 warps, 64x32 warp tile -------------
__global__ __launch_bounds__(256, 2)
void toeplitz_hmma(const float* __restrict__ bias, float* __restrict__ C) {
    extern __shared__ __align__(128) char smem[];
    const uint32_t sb = smem_u32(smem);
    const int tid = threadIdx.x;
    const int lane = tid & 31, wid = tid >> 5;
    const int warp_m = wid >> 2;                   // 0..1 -> 64 rows
    const int warp_n = wid & 3;                    // 0..3 -> 32 cols
    // Longest-first: heavy column blocks (large jb => more causal k-blocks)
    // get the lowest blockIdx so they are dispatched earliest (LPT packing).
    const int jb = (int)gridDim.x - 1 - (int)blockIdx.x;
    const int ib = blockIdx.y;
    const int rowBase = ib * BM, colBase = jb * BN;
    const int nKB = (jb + 1) * 2;                  // causal: k < colBase + BN, BK=64

    float acc[4][4][4];
    #pragma unroll
    for (int i = 0; i < 4; i++)
        #pragma unroll
        for (int j = 0; j < 4; j++)
            #pragma unroll
            for (int k = 0; k < 4; k++) acc[i][j][k] = 0.0f;

    // loader geometry: per tile 128 rows x 128 B; thread t -> row t>>1, 64B half
    const int lrow = tid >> 1;
    const int lc0 = (tid & 1) * 4;                 // first 16B chunk index (0 or 4)
    const __half* gA0 = g_Xhi + (size_t)(rowBase + lrow) * S_DIM + lc0 * 8;
    const __half* gBh = g_Whi + (size_t)(colBase + lrow) * S_DIM + lc0 * 8;
    const uint32_t sRow = lrow * ROWB + lc0 * 16;

    auto issue = [&](int kb) {
        const uint32_t stBase = sb + (kb % NSTAGE) * STAGE;
        const int gk = kb * BK;
        #pragma unroll
        for (int c = 0; c < 4; c++) {
            cp16(stBase + A_HI + sRow + c * 16, gA0 + gk + c * 8);
            cp16(stBase + B_HI + sRow + c * 16, gBh + gk + c * 8);
        }
        asm volatile("cp.async.commit_group;" ::: "memory");
    };

    // ldmatrix per-lane address components
    const int aRow = (lane & 7) + ((lane >> 3) & 1) * 8;  // + m_base
    const uint32_t aKof = (lane >> 4) * 16;               // k-half byte offset
    const int bRow = (lane & 7) + (lane >> 4) * 8;        // + n_base
    const uint32_t bKof = ((lane >> 3) & 1) * 16;

    issue(0);
    if (nKB > 1) issue(1);
    for (int kb = 0; kb < nKB; kb++) {
        if (kb + 1 < nKB) {
            asm volatile("cp.async.wait_group 1;" ::: "memory");
        } else {
            asm volatile("cp.async.wait_group 0;" ::: "memory");
        }
        __syncthreads();               // stage kb visible; stage (kb+2)%3 free
        if (kb + 2 < nKB) issue(kb + 2);

        const uint32_t stBase = sb + (kb % NSTAGE) * STAGE;
        #pragma unroll
        for (int k16 = 0; k16 < 4; k16++) {
            const uint32_t kByte = k16 * 32;
            uint32_t bh[2][4];
            #pragma unroll
            for (int ng = 0; ng < 2; ng++) {
                const int n_base = warp_n * 32 + ng * 16;
                ldsm4(stBase + B_HI + (uint32_t)(n_base + bRow) * ROWB + kByte + bKof, bh[ng]);
            }
            uint32_t ah[4][4];
            #pragma unroll
            for (int mt = 0; mt < 4; mt++) {
                const int m_base = warp_m * 64 + mt * 16;
                ldsm4(stBase + A_HI + (uint32_t)(m_base + aRow) * ROWB + kByte + aKof, ah[mt]);
            }
            #pragma unroll
            for (int mt = 0; mt < 4; mt++)
                #pragma unroll
                for (int ng = 0; ng < 2; ng++) {
                    mma16816(acc[mt][ng * 2 + 0], ah[mt], bh[ng][0], bh[ng][1]);
                    mma16816(acc[mt][ng * 2 + 1], ah[mt], bh[ng][2], bh[ng][3]);
                }
        }
    }

    // ---- epilogue: + bias, float2 stores ----
    #pragma unroll
    for (int mt = 0; mt < 4; mt++) {
        const int r0 = rowBase + warp_m * 64 + mt * 16 + (lane >> 2);
        #pragma unroll
        for (int nt = 0; nt < 4; nt++) {
            const int col = colBase + warp_n * 32 + nt * 8 + (lane & 3) * 2;
            const float2 bv = *reinterpret_cast<const float2*>(bias + col);
            float2 o0, o1;
            o0.x = acc[mt][nt][0] + bv.x; o0.y = acc[mt][nt][1] + bv.y;
            o1.x = acc[mt][nt][2] + bv.x; o1.y = acc[mt][nt][3] + bv.y;
            *reinterpret_cast<float2*>(C + (size_t)r0 * S_DIM + col) = o0;
            *reinterpret_cast<float2*>(C + (size_t)(r0 + 8) * S_DIM + col) = o1;
        }
    }
}

// ------------- launch -------------
extern "C" void kernel_launch(void* const* d_in, const int* in_sizes, int n_in,
                              void* d_out, int out_size) {
    const float* x    = (const float*)d_in[0];   // (32768, 1024)
    const float* w    = (const float*)d_in[1];   // (1, 1024)
    const float* bias = (const float*)d_in[2];   // (1024,)
    float* out = (float*)d_out;
    (void)in_sizes; (void)n_in; (void)out_size;

    cudaFuncSetAttribute(toeplitz_hmma,
                         cudaFuncAttributeMaxDynamicSharedMemorySize, SMEM_TOTAL);

    prepass_kernel<<<XBLOCKS + (S_DIM * S_DIM) / 256, 256>>>(x, w);

    dim3 grid(S_DIM / BN, M_DIM / BM);           // (8, 256)
    toeplitz_hmma<<<grid, 256, SMEM_TOTAL>>>(bias, out);
}